// round 4
// baseline (speedup 1.0000x reference)
#include <cuda_runtime.h>
#include <cstdint>

// AdaptiveSparseVoxels: expand N parents -> 8N children.
// Output (float32): [8N x 32] row-major features, then 8N morton-as-float.
// Row layout: px py pz size dens c0..c26 (32 floats = 128B)
//
// Block = 256 threads = 128 parents. A lane PAIR owns one parent:
//   even lane = low 16 floats (words 0-15) of every child row,
//   odd  lane = high 16 floats (words 16-31).
// Each lane reads its 16-float half of the parent record ONCE (4 LDS.128,
// record stride 36 floats -> balanced 4-way over all bank quads), keeps it
// in registers, and stores it into all 8 child rows (32 STG.128/lane, every
// warp store op = 16 full 32B sectors). Morton codes split by lane parity.

#define TPB 256
#define PPB 128            // parents per block
#define RS  36             // record stride in floats (conflict-balancing pad)

__device__ __forceinline__ unsigned part1by2(unsigned n) {
    n &= 1023u;
    n = (n ^ (n << 16)) & 0xFF0000FFu;
    n = (n ^ (n << 8))  & 0x0300F00Fu;
    n = (n ^ (n << 4))  & 0x030C30C3u;
    n = (n ^ (n << 2))  & 0x09249249u;
    return n;
}

__device__ __forceinline__ unsigned coord_of(float p, float fres, int resm1) {
    // reference: ((p + 1) / 2 * res).astype(int32) then clip(0, res-1)
    float norm = __fmul_rn(__fmul_rn(__fadd_rn(p, 1.0f), 0.5f), fres);
    int c = (int)norm;                 // trunc toward zero == astype(int32)
    c = c < 0 ? 0 : (c > resm1 ? resm1 : c);
    return (unsigned)c;
}

__global__ void __launch_bounds__(TPB)
asv_expand_kernel(
    const float* __restrict__ positions,   // [N,3]
    const float* __restrict__ sizes,       // [N]
    const float* __restrict__ densities,   // [N]
    const float* __restrict__ colors,      // [N,27]
    const int*   __restrict__ level_p,     // [1]
    float*       __restrict__ out,         // [8N*32] + [8N] morton-as-float
    unsigned N, unsigned nrows)            // nrows = 8N
{
    __shared__ __align__(16) float rec[PPB * RS];

    const unsigned tid   = threadIdx.x;
    const unsigned pbase = blockIdx.x * PPB;
    const unsigned nP    = (N - pbase < PPB) ? (N - pbase) : PPB;

    // ---- Stage parent records: [px,py,pz,s,dens,c0..c26] @ stride 36 ----
    for (unsigned i = tid; i < nP * 27u; i += TPB) {
        unsigned p = i / 27u, c = i - p * 27u;
        rec[p * RS + 5u + c] = colors[(pbase + p) * 27u + c];
    }
    for (unsigned i = tid; i < nP * 3u; i += TPB) {
        unsigned p = i / 3u, c = i - p * 3u;
        rec[p * RS + c] = positions[(pbase + p) * 3u + c];
    }
    if (tid < nP) {
        rec[tid * RS + 3u] = sizes[pbase + tid];
        rec[tid * RS + 4u] = densities[pbase + tid];
    }
    __syncthreads();

    const unsigned half = tid & 1u;        // 0: words 0-15, 1: words 16-31
    const unsigned pl   = tid >> 1;        // parent local 0..127
    if (pl >= nP) return;

    const int   res   = 64 << __ldg(level_p);
    const float fres  = (float)res;
    const int   resm1 = res - 1;

    const float* r = &rec[pl * RS];

    // lane's 16-float half of the record, in registers
    const float4 t0 = *reinterpret_cast<const float4*>(r + half * 16u + 0);
    const float4 t1 = *reinterpret_cast<const float4*>(r + half * 16u + 4);
    const float4 t2 = *reinterpret_cast<const float4*>(r + half * 16u + 8);
    const float4 t3 = *reinterpret_cast<const float4*>(r + half * 16u + 12);
    // parent pos+size (even lane already has it in t0)
    const float4 ps = half ? *reinterpret_cast<const float4*>(r) : t0;

    const float s  = ps.w;
    const float qd = 0.25f * s;            // exact
    const float hs = 0.5f  * s;            // exact

    const size_t rowbase = (size_t)(pbase + pl) * 8u;
    float* obase = out + rowbase * 32u;
    float* mbase = out + (size_t)nrows * 32u + rowbase;

    #pragma unroll
    for (int rr = 0; rr < 8; rr++) {
        // child position (cheap; used by head store and/or morton)
        float px = __fadd_rn(ps.x, (rr & 1) ? qd : -qd);
        float py = __fadd_rn(ps.y, (rr & 2) ? qd : -qd);
        float pz = __fadd_rn(ps.z, (rr & 4) ? qd : -qd);

        float* orow = obase + (size_t)rr * 32u + half * 16u;

        float4 v0 = t0;
        if (half == 0u) { v0.x = px; v0.y = py; v0.z = pz; v0.w = hs; }

        *reinterpret_cast<float4*>(orow + 0)  = v0;
        *reinterpret_cast<float4*>(orow + 4)  = t1;
        *reinterpret_cast<float4*>(orow + 8)  = t2;
        *reinterpret_cast<float4*>(orow + 12) = t3;

        // morton: even lane handles even rr, odd lane odd rr
        if ((unsigned)(rr & 1) == half) {
            unsigned code = (part1by2(coord_of(pz, fres, resm1)) << 2)
                          + (part1by2(coord_of(py, fres, resm1)) << 1)
                          +  part1by2(coord_of(px, fres, resm1));
            mbase[rr] = (float)(int)code;   // exact: code < 2^24
        }
    }
}

extern "C" void kernel_launch(void* const* d_in, const int* in_sizes, int n_in,
                              void* d_out, int out_size) {
    const float* positions = (const float*)d_in[0];
    const float* sizes     = (const float*)d_in[1];
    const float* densities = (const float*)d_in[2];
    const float* colors    = (const float*)d_in[3];
    const int*   level     = (const int*)d_in[4];

    unsigned N     = (unsigned)(in_sizes[0] / 3);
    unsigned nrows = N * 8u;

    unsigned blocks = (N + PPB - 1) / PPB;
    asv_expand_kernel<<<blocks, TPB>>>(
        positions, sizes, densities, colors, level,
        (float*)d_out, N, nrows);
}

// round 5
// speedup vs baseline: 2.2541x; 2.2541x over previous
#include <cuda_runtime.h>
#include <cstdint>

// AdaptiveSparseVoxels: expand N parents -> 8N children.
// Output (float32): [8N x 32] row-major features, then 8N morton-as-float.
// Row layout: px py pz size dens c0..c26 (32 floats = 128B)
//
// Mapping: lane i -> column j = i&7 (one float4 of a row), rg = i>>3.
// A warp-op writes 4 consecutive rows x its lane's float4 = 512B FULLY
// CONTIGUOUS (4 cache lines / 4 L1 wavefronts). One parent = 8 rows = 2 ops;
// each lane loads its column float4 from the parent's smem record ONCE
// (conflict-free: 8 distinct 16B addresses = 1 wavefront) and reuses it.
// Smem record is in output layout [px,py,pz,s,dens,c0..c26] so lanes j>=1
// copy verbatim; lane j==0 substitutes child pos/size; lane j==1 computes
// the row's morton code. Streaming stores (no reuse of output).

#define TPB 256
#define WPB 8              // warps per block
#define WP  4              // parents per warp
#define PPB (WPB * WP)     // 32 parents per block

__device__ __forceinline__ unsigned part1by2(unsigned n) {
    n &= 1023u;
    n = (n ^ (n << 16)) & 0xFF0000FFu;
    n = (n ^ (n << 8))  & 0x0300F00Fu;
    n = (n ^ (n << 4))  & 0x030C30C3u;
    n = (n ^ (n << 2))  & 0x09249249u;
    return n;
}

__device__ __forceinline__ unsigned coord_of(float p, float fres, int resm1) {
    // reference: ((p + 1) / 2 * res).astype(int32) then clip(0, res-1)
    float norm = __fmul_rn(__fmul_rn(__fadd_rn(p, 1.0f), 0.5f), fres);
    int c = (int)norm;                 // trunc toward zero == astype(int32)
    c = c < 0 ? 0 : (c > resm1 ? resm1 : c);
    return (unsigned)c;
}

__global__ void __launch_bounds__(TPB)
asv_expand_kernel(
    const float* __restrict__ positions,   // [N,3]
    const float* __restrict__ sizes,       // [N]
    const float* __restrict__ densities,   // [N]
    const float* __restrict__ colors,      // [N,27]
    const int*   __restrict__ level_p,     // [1]
    float*       __restrict__ out,         // [8N*32] + [8N] morton-as-float
    unsigned N, unsigned nrows)            // nrows = 8N
{
    __shared__ __align__(16) float rec[PPB * 32];

    const unsigned tid   = threadIdx.x;
    const unsigned pbase = blockIdx.x * PPB;
    const unsigned nP    = (N - pbase < PPB) ? (N - pbase) : PPB;

    // ---- Stage parent records in OUTPUT layout @ stride 32 floats ----
    for (unsigned i = tid; i < nP * 27u; i += TPB) {
        unsigned p = i / 27u, c = i - p * 27u;
        rec[p * 32u + 5u + c] = colors[(pbase + p) * 27u + c];
    }
    for (unsigned i = tid; i < nP * 3u; i += TPB) {
        unsigned p = i / 3u, c = i - p * 3u;
        rec[p * 32u + c] = positions[(pbase + p) * 3u + c];
    }
    if (tid < nP) {
        rec[tid * 32u + 3u] = sizes[pbase + tid];
        rec[tid * 32u + 4u] = densities[pbase + tid];
    }
    __syncthreads();

    const unsigned lane = tid & 31u;
    const unsigned wid  = tid >> 5;        // warp 0..7
    const unsigned j    = lane & 7u;       // float4 column of the row
    const unsigned rg   = lane >> 3;       // row within 4-row group

    const int   res   = 64 << __ldg(level_p);
    const float fres  = (float)res;
    const int   resm1 = res - 1;

    #pragma unroll
    for (unsigned w = 0; w < WP; w++) {
        const unsigned pl = wid * WP + w;  // parent local 0..31
        if (pl >= nP) break;

        const float* r = &rec[pl * 32u];
        const float4 v  = *reinterpret_cast<const float4*>(r + 4u * j); // own col
        const float4 ps = *reinterpret_cast<const float4*>(r);          // bcast

        const float s  = ps.w;
        const float qd = 0.25f * s;        // exact
        const float hs = 0.5f  * s;        // exact

        const size_t rowbase = (size_t)(pbase + pl) * 8u;
        float* ob = out + rowbase * 32u;

        #pragma unroll
        for (unsigned t = 0; t < 2; t++) {
            const unsigned oct = 4u * t + rg;          // child 0..7

            // child position for THIS lane's row (cheap, all lanes)
            float px = __fadd_rn(ps.x, (oct & 1u) ? qd : -qd);
            float py = __fadd_rn(ps.y, (oct & 2u) ? qd : -qd);
            float pz = __fadd_rn(ps.z, (oct & 4u) ? qd : -qd);

            float4 sv = v;
            if (j == 0u) { sv.x = px; sv.y = py; sv.z = pz; sv.w = hs; }

            __stcs(reinterpret_cast<float4*>(ob + oct * 32u + 4u * j), sv);

            if (j == 1u) {                 // one lane per row does morton
                unsigned code = (part1by2(coord_of(pz, fres, resm1)) << 2)
                              + (part1by2(coord_of(py, fres, resm1)) << 1)
                              +  part1by2(coord_of(px, fres, resm1));
                __stcs(out + (size_t)nrows * 32u + rowbase + oct,
                       (float)(int)code);  // exact: code < 2^21 at level 1
            }
        }
    }
}

extern "C" void kernel_launch(void* const* d_in, const int* in_sizes, int n_in,
                              void* d_out, int out_size) {
    const float* positions = (const float*)d_in[0];
    const float* sizes     = (const float*)d_in[1];
    const float* densities = (const float*)d_in[2];
    const float* colors    = (const float*)d_in[3];
    const int*   level     = (const int*)d_in[4];

    unsigned N     = (unsigned)(in_sizes[0] / 3);
    unsigned nrows = N * 8u;

    unsigned blocks = (N + PPB - 1) / PPB;
    asv_expand_kernel<<<blocks, TPB>>>(
        positions, sizes, densities, colors, level,
        (float*)d_out, N, nrows);
}